// round 4
// baseline (speedup 1.0000x reference)
#include <cuda_runtime.h>
#include <cstdint>

// ROI pooling (TF1 bilinear resize, align_corners=False)
// img:  (1, 1024, 1024, 128) fp32 NHWC
// rois: (1, 512, 4) fp32 = (x1, y1, w, h), integral values
// out:  (1, 512, 7, 7, 128) fp32
//
// R2 design, attempt 3 (attempts 1-2 hit "container failed twice" infra
// errors; kernel never ran). Two output pixels per warp: all 8 tap addresses
// computed first, then 8 independent LDG.128 issued back-to-back (MLP=8 per
// thread) to cover DRAM latency; blend + streaming-store both pixels after.

#define POOL 7
#define NUM_ROIS 512
#define IMG_H 1024
#define IMG_W 1024
#define CH 128
#define PIX_PER_WARP 2

struct TapIdx {
    const float4* p00;
    const float4* p01;
    const float4* p10;
    const float4* p11;
    float fx, fy;
};

__device__ __forceinline__ TapIdx make_taps(
    const float* __restrict__ img, const float* __restrict__ rois,
    int pid, int lane)
{
    const int roi = pid / (POOL * POOL);
    const int pix = pid - roi * (POOL * POOL);
    const int py  = pix / POOL;
    const int px  = pix - py * POOL;

    const float4 r = *reinterpret_cast<const float4*>(rois + roi * 4);
    const int x1 = (int)r.x;
    const int y1 = (int)r.y;
    const int w  = (int)r.z;
    const int h  = (int)r.w;

    const float srcy = (float)py * ((float)h / 7.0f);
    const float srcx = (float)px * ((float)w / 7.0f);

    int ylo = (int)floorf(srcy);
    ylo = min(max(ylo, 0), h - 1);
    const float fy = srcy - (float)ylo;
    const int yhi = min(ylo + 1, h - 1);

    int xlo = (int)floorf(srcx);
    xlo = min(max(xlo, 0), w - 1);
    const float fx = srcx - (float)xlo;
    const int xhi = min(xlo + 1, w - 1);

    const int yloA = min(max(y1 + ylo, 0), IMG_H - 1);
    const int yhiA = min(max(y1 + yhi, 0), IMG_H - 1);
    const int xloA = min(max(x1 + xlo, 0), IMG_W - 1);
    const int xhiA = min(max(x1 + xhi, 0), IMG_W - 1);

    TapIdx t;
    t.p00 = reinterpret_cast<const float4*>(img + ((size_t)yloA * IMG_W + xloA) * CH) + lane;
    t.p01 = reinterpret_cast<const float4*>(img + ((size_t)yloA * IMG_W + xhiA) * CH) + lane;
    t.p10 = reinterpret_cast<const float4*>(img + ((size_t)yhiA * IMG_W + xloA) * CH) + lane;
    t.p11 = reinterpret_cast<const float4*>(img + ((size_t)yhiA * IMG_W + xhiA) * CH) + lane;
    t.fx = fx;
    t.fy = fy;
    return t;
}

__device__ __forceinline__ float4 blend(
    float4 v00, float4 v01, float4 v10, float4 v11, float fx, float fy)
{
    const float gx = 1.0f - fx;
    const float gy = 1.0f - fy;
    float4 o;
    float top, bot;
    top = v00.x * gx + v01.x * fx;  bot = v10.x * gx + v11.x * fx;  o.x = top * gy + bot * fy;
    top = v00.y * gx + v01.y * fx;  bot = v10.y * gx + v11.y * fx;  o.y = top * gy + bot * fy;
    top = v00.z * gx + v01.z * fx;  bot = v10.z * gx + v11.z * fx;  o.z = top * gy + bot * fy;
    top = v00.w * gx + v01.w * fx;  bot = v10.w * gx + v11.w * fx;  o.w = top * gy + bot * fy;
    return o;
}

__global__ __launch_bounds__(256) void roi_pool_kernel(
    const float* __restrict__ img,
    const float* __restrict__ rois,
    float* __restrict__ out)
{
    const int warpInBlock = threadIdx.x >> 5;
    const int lane        = threadIdx.x & 31;
    const int wid  = blockIdx.x * (blockDim.x >> 5) + warpInBlock;
    const int pid0 = wid * PIX_PER_WARP;
    if (pid0 >= NUM_ROIS * POOL * POOL) return;

    // Compute all addresses up front (independent scalar chains).
    const TapIdx tA = make_taps(img, rois, pid0,     lane);
    const TapIdx tB = make_taps(img, rois, pid0 + 1, lane);

    // Issue 8 independent 16B loads back-to-back -> MLP=8 per thread.
    const float4 a00 = __ldg(tA.p00);
    const float4 a01 = __ldg(tA.p01);
    const float4 a10 = __ldg(tA.p10);
    const float4 a11 = __ldg(tA.p11);
    const float4 b00 = __ldg(tB.p00);
    const float4 b01 = __ldg(tB.p01);
    const float4 b10 = __ldg(tB.p10);
    const float4 b11 = __ldg(tB.p11);

    const float4 oA = blend(a00, a01, a10, a11, tA.fx, tA.fy);
    const float4 oB = blend(b00, b01, b10, b11, tB.fx, tB.fy);

    // Output is write-once: streaming store, keep L2 for the gather side.
    float4* dstA = reinterpret_cast<float4*>(out + (size_t)pid0 * CH) + lane;
    float4* dstB = reinterpret_cast<float4*>(out + (size_t)(pid0 + 1) * CH) + lane;
    __stcs(dstA, oA);
    __stcs(dstB, oB);
}

extern "C" void kernel_launch(void* const* d_in, const int* in_sizes, int n_in,
                              void* d_out, int out_size)
{
    const float* img  = (const float*)d_in[0];
    const float* rois = (const float*)d_in[1];
    float* out = (float*)d_out;

    const int totalPixels = NUM_ROIS * POOL * POOL;          // 25088
    const int warps = totalPixels / PIX_PER_WARP;            // 12544
    const int threads = 256;                                 // 8 warps/block
    const int warpsPerBlock = threads / 32;
    const int blocks = (warps + warpsPerBlock - 1) / warpsPerBlock;  // 1568

    roi_pool_kernel<<<blocks, threads>>>(img, rois, out);
}

// round 6
// speedup vs baseline: 1.0625x; 1.0625x over previous
#include <cuda_runtime.h>
#include <cstdint>

// ROI pooling (TF1 bilinear resize, align_corners=False)
// img:  (1, 1024, 1024, 128) fp32 NHWC
// rois: (1, 512, 4) fp32 = (x1, y1, w, h), integral values
// out:  (1, 512, 7, 7, 128) fp32
//
// R5 design, attempt 2 (attempt 1 hit "container failed twice" infra error;
// never ran). 1 pixel/warp (measured-best shape; kernel is DRAM-efficiency-
// bound, not MLP-bound). Skip gather loads whose bilinear weight is exactly
// zero (fx==0 or fy==0): bit-exact vs reference (v*1 + u*0 == v in fp32),
// cuts read traffic ~14-16%. px==0 -> fx=0; py==0 -> fy=0; w%7==0 (h%7==0)
// zeroes fx (fy) for the whole ROI. All conditions warp-uniform.

#define POOL 7
#define NUM_ROIS 512
#define IMG_H 1024
#define IMG_W 1024
#define CH 128

__global__ __launch_bounds__(256) void roi_pool_kernel(
    const float* __restrict__ img,
    const float* __restrict__ rois,
    float* __restrict__ out)
{
    const int warpInBlock = threadIdx.x >> 5;
    const int lane        = threadIdx.x & 31;
    const int pid = blockIdx.x * (blockDim.x >> 5) + warpInBlock; // pixel id
    if (pid >= NUM_ROIS * POOL * POOL) return;

    const int roi = pid / (POOL * POOL);
    const int pix = pid - roi * (POOL * POOL);
    const int py  = pix / POOL;
    const int px  = pix - py * POOL;

    const float4 r = *reinterpret_cast<const float4*>(rois + roi * 4);
    const int x1 = (int)r.x;
    const int y1 = (int)r.y;
    const int w  = (int)r.z;
    const int h  = (int)r.w;

    // TF1 resize: src = dst * (size / POOL), fp32 exactly like the reference
    const float srcy = (float)py * ((float)h / 7.0f);
    const float srcx = (float)px * ((float)w / 7.0f);

    int ylo = (int)floorf(srcy);
    ylo = min(max(ylo, 0), h - 1);
    const float fy = srcy - (float)ylo;
    const int yhi = min(ylo + 1, h - 1);

    int xlo = (int)floorf(srcx);
    xlo = min(max(xlo, 0), w - 1);
    const float fx = srcx - (float)xlo;
    const int xhi = min(xlo + 1, w - 1);

    const int yloA = min(max(y1 + ylo, 0), IMG_H - 1);
    const int yhiA = min(max(y1 + yhi, 0), IMG_H - 1);
    const int xloA = min(max(x1 + xlo, 0), IMG_W - 1);
    const int xhiA = min(max(x1 + xhi, 0), IMG_W - 1);

    // Zero-weight skip flags (warp-uniform; exact-zero test is intentional).
    const bool needX = (fx != 0.0f);
    const bool needY = (fy != 0.0f);

    const float4* p00 = reinterpret_cast<const float4*>(
        img + ((size_t)yloA * IMG_W + xloA) * CH) + lane;
    const float4* p01 = reinterpret_cast<const float4*>(
        img + ((size_t)yloA * IMG_W + xhiA) * CH) + lane;
    const float4* p10 = reinterpret_cast<const float4*>(
        img + ((size_t)yhiA * IMG_W + xloA) * CH) + lane;
    const float4* p11 = reinterpret_cast<const float4*>(
        img + ((size_t)yhiA * IMG_W + xhiA) * CH) + lane;

    // Always need v00. Issue all needed loads back-to-back before consuming.
    const float4 v00 = __ldg(p00);
    float4 v01, v10, v11;
    if (needX)          v01 = __ldg(p01);
    if (needY)          v10 = __ldg(p10);
    if (needX && needY) v11 = __ldg(p11);

    const float gx = 1.0f - fx;
    const float gy = 1.0f - fy;

    float4 o;
    if (needX && needY) {
        float top, bot;
        top = v00.x * gx + v01.x * fx;  bot = v10.x * gx + v11.x * fx;  o.x = top * gy + bot * fy;
        top = v00.y * gx + v01.y * fx;  bot = v10.y * gx + v11.y * fx;  o.y = top * gy + bot * fy;
        top = v00.z * gx + v01.z * fx;  bot = v10.z * gx + v11.z * fx;  o.z = top * gy + bot * fy;
        top = v00.w * gx + v01.w * fx;  bot = v10.w * gx + v11.w * fx;  o.w = top * gy + bot * fy;
    } else if (needX) {
        // fy == 0: out = top exactly (top*1 + bot*0)
        o.x = v00.x * gx + v01.x * fx;
        o.y = v00.y * gx + v01.y * fx;
        o.z = v00.z * gx + v01.z * fx;
        o.w = v00.w * gx + v01.w * fx;
    } else if (needY) {
        // fx == 0: top = v00, bot = v10 exactly
        o.x = v00.x * gy + v10.x * fy;
        o.y = v00.y * gy + v10.y * fy;
        o.z = v00.z * gy + v10.z * fy;
        o.w = v00.w * gy + v10.w * fy;
    } else {
        // fx == fy == 0: out = v00 exactly
        o = v00;
    }

    float4* dst = reinterpret_cast<float4*>(out + (size_t)pid * CH) + lane;
    __stcs(dst, o);
}

extern "C" void kernel_launch(void* const* d_in, const int* in_sizes, int n_in,
                              void* d_out, int out_size)
{
    const float* img  = (const float*)d_in[0];
    const float* rois = (const float*)d_in[1];
    float* out = (float*)d_out;

    const int totalPixels = NUM_ROIS * POOL * POOL;  // 25088
    const int threads = 256;                         // 8 warps = 8 pixels/block
    const int warpsPerBlock = threads / 32;
    const int blocks = (totalPixels + warpsPerBlock - 1) / warpsPerBlock;

    roi_pool_kernel<<<blocks, threads>>>(img, rois, out);
}